// round 11
// baseline (speedup 1.0000x reference)
#include <cuda_runtime.h>
#include <cuda_fp16.h>
#include <math.h>
#include <stdint.h>

#define Bc   16
#define Sc   256
#define Dc   256
#define Hc   128
#define DKc  64
#define NIN  512
#define NJ   1024
#define GRP  8
#define NCH  16
#define CHS  16

// wgemm config
#define NIT    16
#define STG_A  8192
#define STAGE  16384
// pool-gemm config
#define PSTAGE 12288
// yt-gemm config
#define YSTAGE 16384

// ---------------- scratch -----------------
__device__ float g_xtT[Bc * DKc * Sc];
__device__ float g_U[Sc * Bc * NJ];
__device__ float g_cend[NCH * 32 * Hc];
__device__ float g_P[NCH * 32 * Hc];
__device__ float g_yt[Bc * Sc * DKc];                  // [b][s][k]
__device__ __align__(256) __half g_Ah[Sc * Bc * NIN];  // rows ++ pools (fp16)
__device__ __align__(256) __half g_Wh[2 * NJ * NIN];   // [layer][n][k]
__device__ __align__(256) __half g_w2h[8 * DKc * Dc];  // [a][k][d]
__device__ __align__(256) __half g_att[Bc * Sc * Sc];  // [b][s][l]
__device__ __align__(256) __half g_xh[Bc * Sc * Dc];   // x as fp16

// ---------------- helpers -----------------
__device__ __forceinline__ float tanh_fast(float x) {
    float y; asm("tanh.approx.f32 %0, %1;" : "=f"(y) : "f"(x)); return y;
}
__device__ __forceinline__ float sig_fast(float x) {
    float e, r;
    asm("ex2.approx.f32 %0, %1;" : "=f"(e) : "f"(x * -1.4426950408889634f));
    asm("rcp.approx.f32 %0, %1;" : "=f"(r) : "f"(1.0f + e));
    return r;
}
__device__ __forceinline__ uint32_t smem_u32(const void* p) {
    uint32_t a;
    asm("{ .reg .u64 t; cvta.to.shared.u64 t, %1; cvt.u32.u64 %0, t; }" : "=r"(a) : "l"(p));
    return a;
}
__device__ __forceinline__ void cp16(uint32_t d, const void* s) {
    asm volatile("cp.async.cg.shared.global [%0], [%1], 16;\n" :: "r"(d), "l"(s));
}
#define CP_COMMIT() asm volatile("cp.async.commit_group;\n" ::: "memory")
#define CP_WAIT2()  asm volatile("cp.async.wait_group 2;\n" ::: "memory")

__device__ __forceinline__ void ldsm4(uint32_t* r, uint32_t addr) {
    asm volatile("ldmatrix.sync.aligned.m8n8.x4.shared.b16 {%0,%1,%2,%3}, [%4];"
                 : "=r"(r[0]), "=r"(r[1]), "=r"(r[2]), "=r"(r[3]) : "r"(addr));
}
__device__ __forceinline__ void ldsm4t(uint32_t* r, uint32_t addr) {
    asm volatile("ldmatrix.sync.aligned.m8n8.x4.trans.shared.b16 {%0,%1,%2,%3}, [%4];"
                 : "=r"(r[0]), "=r"(r[1]), "=r"(r[2]), "=r"(r[3]) : "r"(addr));
}
__device__ __forceinline__ void mma16816(float* c, const uint32_t* a, const uint32_t* b) {
    asm volatile("mma.sync.aligned.m16n8k16.row.col.f32.f16.f16.f32 "
                 "{%0,%1,%2,%3}, {%4,%5,%6,%7}, {%8,%9}, {%0,%1,%2,%3};"
                 : "+f"(c[0]), "+f"(c[1]), "+f"(c[2]), "+f"(c[3])
                 : "r"(a[0]), "r"(a[1]), "r"(a[2]), "r"(a[3]), "r"(b[0]), "r"(b[1]));
}

// ---------------------------------------------------------------------------
// x -> fp16 (g_xh) and layer-0 rnn-input rows into g_Ah (once)
// ---------------------------------------------------------------------------
__global__ void k_xconv(const float* __restrict__ x) {
    const int e = (blockIdx.x * 256 + threadIdx.x) * 4;
    float4 v = *reinterpret_cast<const float4*>(x + e);
    __half2 h0 = __floats2half2_rn(v.x, v.y);
    __half2 h1 = __floats2half2_rn(v.z, v.w);
    *reinterpret_cast<__half2*>(&g_xh[e])     = h0;
    *reinterpret_cast<__half2*>(&g_xh[e + 2]) = h1;
    const int b = e >> 16, s = (e >> 8) & 255, d = e & 255;
    const size_t idx = (size_t)(s * Bc + b) * NIN + d;
    *reinterpret_cast<__half2*>(&g_Ah[idx])     = h0;
    *reinterpret_cast<__half2*>(&g_Ah[idx + 2]) = h1;
}

// ---------------------------------------------------------------------------
// SRU weight convert+transpose: g_Wh[(l*1024+n)*512+k]
// ---------------------------------------------------------------------------
__global__ void k_wconv(const float* __restrict__ wf, const float* __restrict__ wb) {
    const int k0 = blockIdx.x * 32, nt = blockIdx.y * 32, l = blockIdx.z;
    const float* W = (nt < 512) ? (wf + l * 262144 + nt) : (wb + l * 262144 + (nt - 512));
    __shared__ float t[32][33];
    const int tx = threadIdx.x, ty = threadIdx.y;
    for (int i = ty; i < 32; i += 8)
        t[i][tx] = W[(k0 + i) * 512 + tx];
    __syncthreads();
    for (int i = ty; i < 32; i += 8) {
        size_t idx = (size_t)(l * NJ + nt + i) * NIN + k0 + tx;
        g_Wh[idx] = __float2half(t[tx][i]);
    }
}

// ---------------------------------------------------------------------------
// w2 convert+transpose: g_w2h[a][k][d] from w2[a][d][k]
// ---------------------------------------------------------------------------
__global__ void k_w2conv(const float* __restrict__ w2) {
    const int a = blockIdx.x, dt = blockIdx.y;
    __shared__ float t[32][65];
    const int tid = threadIdx.x;
    for (int i = tid; i < 2048; i += 256) {
        int d = i >> 6, kk = i & 63;
        t[d][kk] = w2[((size_t)a * Dc + dt * 32 + d) * DKc + kk];
    }
    __syncthreads();
    for (int i = tid; i < 2048; i += 256) {
        int kk = i >> 5, d = i & 31;
        g_w2h[((size_t)a * DKc + kk) * Dc + dt * 32 + d] = __float2half(t[d][kk]);
    }
}

// ---------------------------------------------------------------------------
// xtT[b][k][l] = b1[a,k] + sum_d x[b,l,d]*w1[a,d,k]  (256 blocks, fp32)
// ---------------------------------------------------------------------------
__global__ void __launch_bounds__(256) k_xt(
        const float* __restrict__ x, const float* __restrict__ w1,
        const float* __restrict__ b1, const int* __restrict__ act) {
    const int b = blockIdx.x, lt = blockIdx.y;
    const int a = act[b];
    const float* xb = x + b * Sc * Dc + lt * 16 * Dc;
    const float* wa = w1 + a * Dc * DKc;

    __shared__ float xs[16][65];
    __shared__ float ws[64][64];

    const int tid = threadIdx.x;
    const int k = tid & 63, lg = tid >> 6;
    float acc[4] = {};

#pragma unroll
    for (int d0 = 0; d0 < Dc; d0 += 64) {
#pragma unroll
        for (int i = 0; i < 4; i++) {
            int v = tid + i * 256, l = v >> 6, d = v & 63;
            xs[l][d] = xb[l * Dc + d0 + d];
        }
#pragma unroll
        for (int i = 0; i < 16; i++) {
            int v = tid + i * 256, d = v >> 6, kk = v & 63;
            ws[d][kk] = wa[(d0 + d) * DKc + kk];
        }
        __syncthreads();
#pragma unroll 8
        for (int d = 0; d < 64; d++) {
            float w = ws[d][k];
#pragma unroll
            for (int i = 0; i < 4; i++)
                acc[i] = fmaf(xs[lg * 4 + i][d], w, acc[i]);
        }
        __syncthreads();
    }
    const float bb = b1[a * DKc + k];
#pragma unroll
    for (int i = 0; i < 4; i++) {
        int l = lt * 16 + lg * 4 + i;
        g_xtT[b * (DKc * Sc) + k * Sc + l] = acc[i] + bb;
    }
}

// ---------------------------------------------------------------------------
// yt GEMM (HMMA): g_yt[b][s][k] = rows(g_Ah) @ w2a^T + b2
// grid (16 b, 4 st): M=64 s-rows, N=64 k, K=256 d. 3-stage cp.async.
// ---------------------------------------------------------------------------
__device__ __forceinline__ void y_load(int c, int tid, uint32_t sb, int b, int st, int a) {
    const int d0 = c << 6;
    const uint32_t ab = sb + (c % 3) * YSTAGE;
    const uint32_t bb = ab + 8192;
#pragma unroll
    for (int i = 0; i < 2; i++) {
        int v = tid + i * 256, r = v >> 3, ch = v & 7;
        const __half* src = g_Ah + (size_t)((st * 64 + r) * Bc + b) * NIN + d0 + ch * 8;
        cp16(ab + r * 128 + ((ch ^ (r & 7)) << 4), src);
    }
#pragma unroll
    for (int i = 0; i < 2; i++) {
        int v = tid + i * 256, r = v >> 3, ch = v & 7;
        const __half* src = g_w2h + (size_t)(a * DKc + r) * Dc + d0 + ch * 8;
        cp16(bb + r * 128 + ((ch ^ (r & 7)) << 4), src);
    }
}

__global__ void __launch_bounds__(256) k_ytg(const int* __restrict__ act,
                                             const float* __restrict__ b2) {
    __shared__ __align__(128) char sm[3 * YSTAGE];
    const uint32_t sb = smem_u32(sm);
    const int tid = threadIdx.x, wid = tid >> 5, lane = tid & 31;
    const int b = blockIdx.x, st = blockIdx.y;
    const int a = act[b];
    const int wm = wid & 3, wn = wid >> 2;

    float acc[4][4] = {};

    y_load(0, tid, sb, b, st, a); CP_COMMIT();
    y_load(1, tid, sb, b, st, a); CP_COMMIT();

    for (int c = 0; c < 4; c++) {
        if (c + 2 < 4) y_load(c + 2, tid, sb, b, st, a);
        CP_COMMIT();
        CP_WAIT2();
        __syncthreads();
        const uint32_t ab = sb + (c % 3) * YSTAGE;
        const uint32_t bb = ab + 8192;
#pragma unroll
        for (int ks = 0; ks < 4; ks++) {
            const int k8 = ks * 2 + (lane >> 4);
            uint32_t afr[4];
            {
                int r = wm * 16 + (lane & 15);
                ldsm4(afr, ab + r * 128 + ((k8 ^ (r & 7)) << 4));
            }
            uint32_t bfr[4][2];
#pragma unroll
            for (int np = 0; np < 2; np++) {
                int r = wn * 32 + np * 16 + (lane & 15);
                uint32_t t[4];
                ldsm4(t, bb + r * 128 + ((k8 ^ (r & 7)) << 4));
                bfr[np * 2][0] = t[0]; bfr[np * 2 + 1][0] = t[1];
                bfr[np * 2][1] = t[2]; bfr[np * 2 + 1][1] = t[3];
            }
#pragma unroll
            for (int nt2 = 0; nt2 < 4; nt2++)
                mma16816(acc[nt2], afr, bfr[nt2]);
        }
        __syncthreads();
    }

    const int s = st * 64 + wm * 16 + (lane >> 2);
    const int n0 = wn * 32 + (lane & 3) * 2;
#pragma unroll
    for (int nt2 = 0; nt2 < 4; nt2++) {
        int n = n0 + nt2 * 8;
        float b0 = b2[a * DKc + n], b1v = b2[a * DKc + n + 1];
        float* dst = g_yt + ((size_t)b * Sc + s) * DKc + n;
        *reinterpret_cast<float2*>(dst) =
            make_float2(acc[nt2][0] + b0, acc[nt2][1] + b1v);
        *reinterpret_cast<float2*>(dst + 8 * DKc) =
            make_float2(acc[nt2][2] + b0, acc[nt2][3] + b1v);
    }
}

// ---------------------------------------------------------------------------
// Attention scores+softmax (slim): reads g_yt + g_xtT, writes g_att only.
// ---------------------------------------------------------------------------
__global__ void __launch_bounds__(256) k_attn(
        const unsigned char* __restrict__ mask,
        const int* __restrict__ act,
        const float* __restrict__ v) {
    const int s0 = blockIdx.x * GRP;
    const int b = blockIdx.y;
    const int a = act[b];
    const int tid = threadIdx.x;

    __shared__ __align__(16) float yt2[DKc][GRP];
    __shared__ float vv[DKc];
    __shared__ float red[8][GRP];
    __shared__ float ginv[GRP];

    const bool msk = mask[b * Sc + tid];
    if (tid < DKc) vv[tid] = v[a * DKc + tid];
    for (int idx = tid; idx < DKc * GRP; idx += 256) {
        int k = idx >> 3, g = idx & 7;
        yt2[k][g] = g_yt[((size_t)b * Sc + s0 + g) * DKc + k];
    }
    __syncthreads();

    // scores: thread = memory position l = tid, all 8 s rows
    float sc[GRP] = {};
    {
        const float* xt = g_xtT + b * (DKc * Sc);
        for (int k0 = 0; k0 < DKc; k0 += 8) {
            float xvv[8];
#pragma unroll
            for (int kk = 0; kk < 8; kk++)
                xvv[kk] = xt[(k0 + kk) * Sc + tid];
#pragma unroll
            for (int kk = 0; kk < 8; kk++) {
                const int k = k0 + kk;
                const float vk = vv[k];
                const float xv = xvv[kk];
                float4 y0 = *reinterpret_cast<const float4*>(&yt2[k][0]);
                float4 y1 = *reinterpret_cast<const float4*>(&yt2[k][4]);
                sc[0] = fmaf(vk, tanh_fast(xv + y0.x), sc[0]);
                sc[1] = fmaf(vk, tanh_fast(xv + y0.y), sc[1]);
                sc[2] = fmaf(vk, tanh_fast(xv + y0.z), sc[2]);
                sc[3] = fmaf(vk, tanh_fast(xv + y0.w), sc[3]);
                sc[4] = fmaf(vk, tanh_fast(xv + y1.x), sc[4]);
                sc[5] = fmaf(vk, tanh_fast(xv + y1.y), sc[5]);
                sc[6] = fmaf(vk, tanh_fast(xv + y1.z), sc[6]);
                sc[7] = fmaf(vk, tanh_fast(xv + y1.w), sc[7]);
            }
        }
    }

    // softmax without max-subtraction (|score| <= sum|v| <= 8)
    const int lane = tid & 31, wid = tid >> 5;
    float ex[GRP];
#pragma unroll
    for (int g = 0; g < GRP; g++) ex[g] = msk ? 0.0f : __expf(sc[g]);
#pragma unroll
    for (int g = 0; g < GRP; g++) {
        float s = ex[g];
#pragma unroll
        for (int o = 16; o > 0; o >>= 1) s += __shfl_xor_sync(0xffffffffu, s, o);
        if (lane == 0) red[wid][g] = s;
    }
    __syncthreads();
    if (tid < GRP) {
        float s = red[0][tid];
#pragma unroll
        for (int w = 1; w < 8; w++) s += red[w][tid];
        ginv[tid] = 1.0f / s;
    }
    __syncthreads();

#pragma unroll
    for (int g = 0; g < GRP; g++)
        g_att[((size_t)b * Sc + s0 + g) * Sc + tid] = __float2half(ex[g] * ginv[g]);
}

// ---------------------------------------------------------------------------
// Pools GEMM: pools = att @ x (HMMA), writes fp16 into g_Ah[...,256+d]
// ---------------------------------------------------------------------------
__device__ __forceinline__ void p_load(int c, int tid, uint32_t sb,
                                       int b, int st, int nt) {
    const int l0 = c << 5;
    const uint32_t ab = sb + (c % 3) * PSTAGE;
    const uint32_t bb = ab + 4096;
    {
        int r = tid >> 2, ch = tid & 3;
        const __half* src = g_att + ((size_t)b * Sc + st * 64 + r) * Sc + l0 + ch * 8;
        cp16(ab + r * 64 + ((ch ^ (r & 3)) << 4), src);
    }
#pragma unroll
    for (int i = 0; i < 2; i++) {
        int v = tid + i * 256, r = v >> 4, ch = v & 15;
        const __half* src = g_xh + ((size_t)b * Sc + l0 + r) * Dc + nt * 128 + ch * 8;
        cp16(bb + r * 256 + ((ch ^ (r & 15)) << 4), src);
    }
}

__global__ void __launch_bounds__(256) k_pool() {
    __shared__ __align__(128) char sm[3 * PSTAGE];
    const uint32_t sb = smem_u32(sm);
    const int tid = threadIdx.x, wid = tid >> 5, lane = tid & 31;
    const int b = blockIdx.x, st = blockIdx.y, nt = blockIdx.z;
    const int wm = wid & 1, wn = wid >> 1;

    float acc[2][4][4] = {};

    p_load(0, tid, sb, b, st, nt); CP_COMMIT();
    p_load(1, tid, sb, b, st, nt); CP_COMMIT();

    for (int c = 0; c < 8; c++) {
        if (c + 2 < 8) p_load(c + 2, tid, sb, b, st, nt);
        CP_COMMIT();
        CP_WAIT2();
        __syncthreads();

        const uint32_t ab = sb + (c % 3) * PSTAGE;
        const uint32_t bb = ab + 4096;
#pragma unroll
        for (int ks = 0; ks < 2; ks++) {
            uint32_t a[2][4];
#pragma unroll
            for (int mt2 = 0; mt2 < 2; mt2++) {
                int r = wm * 32 + mt2 * 16 + (lane & 15);
                int k8 = ks * 2 + (lane >> 4);
                ldsm4(a[mt2], ab + r * 64 + ((k8 ^ (r & 3)) << 4));
            }
            uint32_t bf[4][2];
#pragma unroll
            for (int ng = 0; ng < 2; ng++) {
                int r = ks * 16 + (lane & 15);
                int ch = wn * 4 + ng * 2 + (lane >> 4);
                uint32_t t[4];
                ldsm4t(t, bb + r * 256 + ((ch ^ (r & 15)) << 4));
                bf[ng * 2][0] = t[0]; bf[ng * 2][1] = t[1];
                bf[ng * 2 + 1][0] = t[2]; bf[ng * 2 + 1][1] = t[3];
            }
#pragma unroll
            for (int mt2 = 0; mt2 < 2; mt2++)
#pragma unroll
                for (int oct = 0; oct < 4; oct++)
                    mma16816(acc[mt2][oct], a[mt2], bf[oct]);
        }
        __syncthreads();
    }

    const int s_b = st * 64 + wm * 32 + (lane >> 2);
    const int d_b = nt * 128 + wn * 32 + (lane & 3) * 2;
#pragma unroll
    for (int mt2 = 0; mt2 < 2; mt2++) {
#pragma unroll
        for (int oct = 0; oct < 4; oct++) {
            int s = s_b + mt2 * 16, d = d_b + oct * 8;
            __half2 h01 = __floats2half2_rn(acc[mt2][oct][0], acc[mt2][oct][1]);
            __half2 h23 = __floats2half2_rn(acc[mt2][oct][2], acc[mt2][oct][3]);
            *reinterpret_cast<__half2*>(&g_Ah[(size_t)(s * Bc + b) * NIN + Dc + d]) = h01;
            *reinterpret_cast<__half2*>(&g_Ah[(size_t)((s + 8) * Bc + b) * NIN + Dc + d]) = h23;
        }
    }
}

// ---------------------------------------------------------------------------
// HMMA GEMM: U = Ah @ Wh^T
// ---------------------------------------------------------------------------
__device__ __forceinline__ void g_load(int c, int tid, uint32_t sb,
                                       int mt, int nt, int layer) {
    const int kc = c << 5;
    const __half* Ap = g_Ah + (size_t)(mt * 128) * NIN + kc;
    const __half* Bp = g_Wh + (size_t)(layer * NJ + nt * 128) * NIN + kc;
    const uint32_t ab = sb + (c % 3) * STAGE;
    const uint32_t bb = ab + STG_A;
#pragma unroll
    for (int i = 0; i < 2; i++) {
        int vi = tid + i * 256, r = vi >> 2, ch = vi & 3;
        cp16(ab + r * 64 + ((ch ^ (r & 3)) << 4), Ap + (size_t)r * NIN + ch * 8);
    }
#pragma unroll
    for (int i = 0; i < 2; i++) {
        int vi = tid + i * 256, r = vi >> 2, ch = vi & 3;
        cp16(bb + r * 64 + ((ch ^ (r & 3)) << 4), Bp + (size_t)r * NIN + ch * 8);
    }
}

__global__ void __launch_bounds__(256) k_wgemm(int layer) {
    __shared__ __align__(128) char sm[3 * STAGE];
    const uint32_t sb = smem_u32(sm);
    const int tid = threadIdx.x, wid = tid >> 5, lane = tid & 31;
    const int mt = blockIdx.x, nt = blockIdx.y;
    const int wm = wid & 3, wn = wid >> 2;

    float acc[2][8][4] = {};

    g_load(0, tid, sb, mt, nt, layer); CP_COMMIT();
    g_load(1, tid, sb, mt, nt, layer); CP_COMMIT();

    const int arow_b = wm * 32 + (lane & 15);
    const int brow_b = wn * 64 + (lane & 15);
    const int khalf = lane >> 4;

    for (int c = 0; c < NIT; c++) {
        if (c + 2 < NIT) g_load(c + 2, tid, sb, mt, nt, layer);
        CP_COMMIT();
        CP_WAIT2();
        __syncthreads();

        const uint32_t ab = sb + (c % 3) * STAGE;
        const uint32_t bb = ab + STG_A;
#pragma unroll
        for (int ks = 0; ks < 2; ks++) {
            const int k8 = ks * 2 + khalf;
            uint32_t a[2][4], b[8][2];
#pragma unroll
            for (int mtile = 0; mtile < 2; mtile++) {
                int r = arow_b + mtile * 16;
                ldsm4(a[mtile], ab + r * 64 + ((k8 ^ (r & 3)) << 4));
            }
#pragma unroll
            for (int np = 0; np < 4; np++) {
                int r = brow_b + np * 16;
                uint32_t t[4];
                ldsm4(t, bb + r * 64 + ((k8 ^ (r & 3)) << 4));
                b[np * 2][0] = t[0]; b[np * 2 + 1][0] = t[1];
                b[np * 2][1] = t[2]; b[np * 2 + 1][1] = t[3];
            }
#pragma unroll
            for (int mtile = 0; mtile < 2; mtile++)
#pragma unroll
                for (int ntile = 0; ntile < 8; ntile++)
                    mma16816(acc[mtile][ntile], a[mtile], b[ntile]);
        }
        __syncthreads();
    }

    const int m_b = mt * 128 + wm * 32 + (lane >> 2);
    const int n_b = nt * 128 + wn * 64 + (lane & 3) * 2;
#pragma unroll
    for (int mtile = 0; mtile < 2; mtile++) {
#pragma unroll
        for (int ntile = 0; ntile < 8; ntile++) {
            float* dst = g_U + (size_t)(m_b + mtile * 16) * NJ + n_b + ntile * 8;
            *reinterpret_cast<float2*>(dst) =
                make_float2(acc[mtile][ntile][0], acc[mtile][ntile][1]);
            *reinterpret_cast<float2*>(dst + 8 * NJ) =
                make_float2(acc[mtile][ntile][2], acc[mtile][ntile][3]);
        }
    }
}

// ---------------------------------------------------------------------------
// SRU chunked-parallel scan with batched prefetch
// ---------------------------------------------------------------------------
__global__ void k_scanA(const float* __restrict__ bfv, const float* __restrict__ bbv,
                        int layer) {
    const int ch = blockIdx.x, by = blockIdx.y;
    const int b = by >> 1, dir = by & 1;
    const int h = threadIdx.x;
    const float bf = ((dir == 0 ? bfv : bbv) + layer * 2 * Hc)[h];
    const float* base = g_U + ((size_t)(ch * CHS) * Bc + b) * NJ + dir * 512 + h;

    float u0v[CHS], ufv[CHS];
#pragma unroll
    for (int s = 0; s < CHS; s++) {
        const float* u = base + (size_t)s * (Bc * NJ);
        u0v[s] = u[0];
        ufv[s] = u[128];
    }
    float c = 0.0f, P = 1.0f;
#pragma unroll
    for (int s = 0; s < CHS; s++) {
        float f = sig_fast(ufv[s] + bf);
        c = u0v[s] + f * (c - u0v[s]);
        P *= f;
    }
    const int idx = (ch * 32 + by) * Hc + h;
    g_cend[idx] = c;
    g_P[idx] = P;
}

__global__ void k_scanC(const float* __restrict__ bfv, const float* __restrict__ bbv,
                        int layer, int is_last, float* __restrict__ out_final) {
    const int ch = blockIdx.x, by = blockIdx.y;
    const int b = by >> 1, dir = by & 1;
    const int h = threadIdx.x;
    const float* bias = (dir == 0 ? bfv : bbv) + layer * 2 * Hc;
    const float bf = bias[h];
    const float br = bias[Hc + h];
    const float* base = g_U + ((size_t)(ch * CHS) * Bc + b) * NJ + dir * 512 + h;

    float c = 0.0f;
    {
        float Pa[NCH - 1], Ca[NCH - 1];
#pragma unroll
        for (int i = 0; i < NCH - 1; i++) {
            if (i < ch) {
                const int idx = (i * 32 + by) * Hc + h;
                Pa[i] = g_P[idx];
                Ca[i] = g_cend[idx];
            }
        }
#pragma unroll
        for (int i = 0; i < NCH - 1; i++)
            if (i < ch) c = Pa[i] * c + Ca[i];
    }

#pragma unroll
    for (int half = 0; half < 2; half++) {
        float u0v[8], ufv[8], urv[8], hwv[8];
#pragma unroll
        for (int s = 0; s < 8; s++) {
            const float* u = base + (size_t)(half * 8 + s) * (Bc * NJ);
            u0v[s] = u[0]; ufv[s] = u[128]; urv[s] = u[256]; hwv[s] = u[384];
        }
#pragma unroll
        for (int s = 0; s < 8; s++) {
            float f = sig_fast(ufv[s] + bf);
            float r = sig_fast(urv[s] + br);
            c = u0v[s] + f * (c - u0v[s]);
            float hv = hwv[s] + r * (tanh_fast(c) - hwv[s]);
            const int s_abs = ch * CHS + half * 8 + s;
            if (is_last)
                out_final[b * (Sc * Dc) + s_abs * Dc + dir * Hc + h] = hv;
            else
                g_Ah[(size_t)(s_abs * Bc + b) * NIN + dir * Hc + h] = __float2half(hv);
        }
    }
}

// ---------------------------------------------------------------------------
extern "C" void kernel_launch(void* const* d_in, const int* in_sizes, int n_in,
                              void* d_out, int out_size) {
    const float* x            = (const float*)d_in[0];
    const unsigned char* mask = (const unsigned char*)d_in[1];
    const int* act            = (const int*)d_in[2];
    const float* w1           = (const float*)d_in[3];
    const float* b1           = (const float*)d_in[4];
    const float* w2           = (const float*)d_in[5];
    const float* b2           = (const float*)d_in[6];
    const float* v            = (const float*)d_in[7];
    const float* swf          = (const float*)d_in[8];
    const float* sbf          = (const float*)d_in[9];
    const float* swb          = (const float*)d_in[10];
    const float* sbb          = (const float*)d_in[11];
    float* out = (float*)d_out;

    k_xconv<<<Bc * Sc * Dc / 1024, 256>>>(x);
    k_wconv<<<dim3(16, 32, 2), dim3(32, 8)>>>(swf, swb);
    k_w2conv<<<dim3(8, 8), 256>>>(w2);
    k_xt<<<dim3(Bc, 16), 256>>>(x, w1, b1, act);

    for (int layer = 0; layer < 2; layer++) {
        k_ytg<<<dim3(Bc, 4), 256>>>(act, b2);
        k_attn<<<dim3(Sc / GRP, Bc), 256>>>(mask, act, v);
        k_pool<<<dim3(Bc, 4, 2), 256>>>();
        k_wgemm<<<dim3(32, 8), 256>>>(layer);
        k_scanA<<<dim3(NCH, 32), Hc>>>(sbf, sbb, layer);
        k_scanC<<<dim3(NCH, 32), Hc>>>(sbf, sbb, layer, layer == 1 ? 1 : 0, out);
    }
}

// round 15
// speedup vs baseline: 1.0923x; 1.0923x over previous
#include <cuda_runtime.h>
#include <cuda_fp16.h>
#include <math.h>
#include <stdint.h>

#define Bc   16
#define Sc   256
#define Dc   256
#define Hc   128
#define DKc  64
#define NIN  512
#define NJ   1024
#define GRP  8
#define NCH  16
#define CHS  16

// wgemm config
#define NIT    16
#define STG_A  8192
#define STAGE  16384
// pool-gemm config
#define PSTAGE 12288
// yt/xt-gemm config
#define YSTAGE 16384

// ---------------- scratch -----------------
__device__ float g_xtT[Bc * DKc * Sc];
__device__ float g_U[Sc * Bc * NJ];
__device__ float g_cend[NCH * 32 * Hc];
__device__ float g_P[NCH * 32 * Hc];
__device__ float g_yt[Bc * Sc * DKc];                  // [b][s][k]
__device__ __align__(256) __half g_Ah[Sc * Bc * NIN];  // rows ++ pools (fp16)
__device__ __align__(256) __half g_Wh[2 * NJ * NIN];   // [layer][n][k]
__device__ __align__(256) __half g_w2h[8 * DKc * Dc];  // [a][k][d]
__device__ __align__(256) __half g_w1h[8 * DKc * Dc];  // [a][k][d]
__device__ __align__(256) __half g_att[Bc * Sc * Sc];  // [b][s][l]
__device__ __align__(256) __half g_xh[Bc * Sc * Dc];   // x as fp16

// ---------------- helpers -----------------
__device__ __forceinline__ float tanh_fast(float x) {
    float y; asm("tanh.approx.f32 %0, %1;" : "=f"(y) : "f"(x)); return y;
}
__device__ __forceinline__ float sig_fast(float x) {
    float e, r;
    asm("ex2.approx.f32 %0, %1;" : "=f"(e) : "f"(x * -1.4426950408889634f));
    asm("rcp.approx.f32 %0, %1;" : "=f"(r) : "f"(1.0f + e));
    return r;
}
__device__ __forceinline__ uint32_t smem_u32(const void* p) {
    uint32_t a;
    asm("{ .reg .u64 t; cvta.to.shared.u64 t, %1; cvt.u32.u64 %0, t; }" : "=r"(a) : "l"(p));
    return a;
}
__device__ __forceinline__ void cp16(uint32_t d, const void* s) {
    asm volatile("cp.async.cg.shared.global [%0], [%1], 16;\n" :: "r"(d), "l"(s));
}
#define CP_COMMIT() asm volatile("cp.async.commit_group;\n" ::: "memory")
#define CP_WAIT2()  asm volatile("cp.async.wait_group 2;\n" ::: "memory")

__device__ __forceinline__ void ldsm4(uint32_t* r, uint32_t addr) {
    asm volatile("ldmatrix.sync.aligned.m8n8.x4.shared.b16 {%0,%1,%2,%3}, [%4];"
                 : "=r"(r[0]), "=r"(r[1]), "=r"(r[2]), "=r"(r[3]) : "r"(addr));
}
__device__ __forceinline__ void ldsm4t(uint32_t* r, uint32_t addr) {
    asm volatile("ldmatrix.sync.aligned.m8n8.x4.trans.shared.b16 {%0,%1,%2,%3}, [%4];"
                 : "=r"(r[0]), "=r"(r[1]), "=r"(r[2]), "=r"(r[3]) : "r"(addr));
}
__device__ __forceinline__ void mma16816(float* c, const uint32_t* a, const uint32_t* b) {
    asm volatile("mma.sync.aligned.m16n8k16.row.col.f32.f16.f16.f32 "
                 "{%0,%1,%2,%3}, {%4,%5,%6,%7}, {%8,%9}, {%0,%1,%2,%3};"
                 : "+f"(c[0]), "+f"(c[1]), "+f"(c[2]), "+f"(c[3])
                 : "r"(a[0]), "r"(a[1]), "r"(a[2]), "r"(a[3]), "r"(b[0]), "r"(b[1]));
}

// ---------------------------------------------------------------------------
// k_prep: merged prep dispatch.
//   blocks [0,1024):    x -> fp16 g_xh + layer-0 rows into g_Ah
//   blocks [1024,2048): SRU weight convert/transpose -> g_Wh
//   blocks [2048,2176): w2/w1 convert/transpose -> g_w2h / g_w1h
// ---------------------------------------------------------------------------
__global__ void __launch_bounds__(256) k_prep(
        const float* __restrict__ x,
        const float* __restrict__ wf, const float* __restrict__ wb,
        const float* __restrict__ w2, const float* __restrict__ w1) {
    __shared__ float t[32][65];
    const int blk = blockIdx.x, tid = threadIdx.x;

    if (blk < 1024) {
        const int e = (blk * 256 + tid) * 4;
        float4 v = *reinterpret_cast<const float4*>(x + e);
        __half2 h0 = __floats2half2_rn(v.x, v.y);
        __half2 h1 = __floats2half2_rn(v.z, v.w);
        *reinterpret_cast<__half2*>(&g_xh[e])     = h0;
        *reinterpret_cast<__half2*>(&g_xh[e + 2]) = h1;
        const int b = e >> 16, s = (e >> 8) & 255, d = e & 255;
        const size_t idx = (size_t)(s * Bc + b) * NIN + d;
        *reinterpret_cast<__half2*>(&g_Ah[idx])     = h0;
        *reinterpret_cast<__half2*>(&g_Ah[idx + 2]) = h1;
    } else if (blk < 2048) {
        const int idx = blk - 1024;
        const int k0 = (idx & 15) * 32;
        const int nt = ((idx >> 4) & 31) * 32;
        const int l = idx >> 9;
        const float* W = (nt < 512) ? (wf + l * 262144 + nt)
                                    : (wb + l * 262144 + (nt - 512));
        const int tx = tid & 31, ty = tid >> 5;
        for (int i = ty; i < 32; i += 8)
            t[i][tx] = W[(k0 + i) * 512 + tx];
        __syncthreads();
        for (int i = ty; i < 32; i += 8) {
            size_t o = (size_t)(l * NJ + nt + i) * NIN + k0 + tx;
            g_Wh[o] = __float2half(t[tx][i]);
        }
    } else {
        const int idx = blk - 2048;            // [0,128): 64 w2 then 64 w1
        const float* W = (idx < 64) ? w2 : w1;
        __half* dst = (idx < 64) ? g_w2h : g_w1h;
        const int a = (idx & 63) >> 3, dt = idx & 7;
        for (int i = tid; i < 2048; i += 256) {
            int d = i >> 6, kk = i & 63;
            t[d][kk] = W[((size_t)a * Dc + dt * 32 + d) * DKc + kk];
        }
        __syncthreads();
        for (int i = tid; i < 2048; i += 256) {
            int kk = i >> 5, d = i & 31;
            dst[((size_t)a * DKc + kk) * Dc + dt * 32 + d] = __float2half(t[d][kk]);
        }
    }
}

// ---------------------------------------------------------------------------
// xt GEMM (HMMA): g_xtT[b][k][l] = x[b,l,:] @ w1a[:,k] + b1
// grid (16 b, 4 lt): M=64 l-rows, N=64 k, K=256 d. 3-stage cp.async.
// ---------------------------------------------------------------------------
__device__ __forceinline__ void x_load(int c, int tid, uint32_t sb, int b, int lt, int a) {
    const int d0 = c << 6;
    const uint32_t ab = sb + (c % 3) * YSTAGE;
    const uint32_t bb = ab + 8192;
#pragma unroll
    for (int i = 0; i < 2; i++) {
        int v = tid + i * 256, r = v >> 3, ch = v & 7;
        const __half* src = g_xh + (size_t)(b * Sc + lt * 64 + r) * Dc + d0 + ch * 8;
        cp16(ab + r * 128 + ((ch ^ (r & 7)) << 4), src);
    }
#pragma unroll
    for (int i = 0; i < 2; i++) {
        int v = tid + i * 256, r = v >> 3, ch = v & 7;
        const __half* src = g_w1h + (size_t)(a * DKc + r) * Dc + d0 + ch * 8;
        cp16(bb + r * 128 + ((ch ^ (r & 7)) << 4), src);
    }
}

__global__ void __launch_bounds__(256) k_xtg(const int* __restrict__ act,
                                             const float* __restrict__ b1) {
    __shared__ __align__(128) char sm[3 * YSTAGE];
    const uint32_t sb = smem_u32(sm);
    const int tid = threadIdx.x, wid = tid >> 5, lane = tid & 31;
    const int b = blockIdx.x, lt = blockIdx.y;
    const int a = act[b];
    const int wm = wid & 3, wn = wid >> 2;

    float acc[4][4] = {};

    x_load(0, tid, sb, b, lt, a); CP_COMMIT();
    x_load(1, tid, sb, b, lt, a); CP_COMMIT();

    for (int c = 0; c < 4; c++) {
        if (c + 2 < 4) x_load(c + 2, tid, sb, b, lt, a);
        CP_COMMIT();
        CP_WAIT2();
        __syncthreads();
        const uint32_t ab = sb + (c % 3) * YSTAGE;
        const uint32_t bb = ab + 8192;
#pragma unroll
        for (int ks = 0; ks < 4; ks++) {
            const int k8 = ks * 2 + (lane >> 4);
            uint32_t afr[4];
            {
                int r = wm * 16 + (lane & 15);
                ldsm4(afr, ab + r * 128 + ((k8 ^ (r & 7)) << 4));
            }
            uint32_t bfr[4][2];
#pragma unroll
            for (int np = 0; np < 2; np++) {
                int r = wn * 32 + np * 16 + (lane & 15);
                uint32_t t[4];
                ldsm4(t, bb + r * 128 + ((k8 ^ (r & 7)) << 4));
                bfr[np * 2][0] = t[0]; bfr[np * 2 + 1][0] = t[1];
                bfr[np * 2][1] = t[2]; bfr[np * 2 + 1][1] = t[3];
            }
#pragma unroll
            for (int nt2 = 0; nt2 < 4; nt2++)
                mma16816(acc[nt2], afr, bfr[nt2]);
        }
        __syncthreads();
    }

    const int l = lt * 64 + wm * 16 + (lane >> 2);
    const int n0 = wn * 32 + (lane & 3) * 2;
    float* xt = g_xtT + b * (DKc * Sc);
#pragma unroll
    for (int nt2 = 0; nt2 < 4; nt2++) {
        int n = n0 + nt2 * 8;
        float b0 = b1[a * DKc + n], b1v = b1[a * DKc + n + 1];
        xt[n * Sc + l]           = acc[nt2][0] + b0;
        xt[(n + 1) * Sc + l]     = acc[nt2][1] + b1v;
        xt[n * Sc + l + 8]       = acc[nt2][2] + b0;
        xt[(n + 1) * Sc + l + 8] = acc[nt2][3] + b1v;
    }
}

// ---------------------------------------------------------------------------
// yt GEMM (HMMA): g_yt[b][s][k] = rows(g_Ah) @ w2a^T + b2
// ---------------------------------------------------------------------------
__device__ __forceinline__ void y_load(int c, int tid, uint32_t sb, int b, int st, int a) {
    const int d0 = c << 6;
    const uint32_t ab = sb + (c % 3) * YSTAGE;
    const uint32_t bb = ab + 8192;
#pragma unroll
    for (int i = 0; i < 2; i++) {
        int v = tid + i * 256, r = v >> 3, ch = v & 7;
        const __half* src = g_Ah + (size_t)((st * 64 + r) * Bc + b) * NIN + d0 + ch * 8;
        cp16(ab + r * 128 + ((ch ^ (r & 7)) << 4), src);
    }
#pragma unroll
    for (int i = 0; i < 2; i++) {
        int v = tid + i * 256, r = v >> 3, ch = v & 7;
        const __half* src = g_w2h + (size_t)(a * DKc + r) * Dc + d0 + ch * 8;
        cp16(bb + r * 128 + ((ch ^ (r & 7)) << 4), src);
    }
}

__global__ void __launch_bounds__(256) k_ytg(const int* __restrict__ act,
                                             const float* __restrict__ b2) {
    __shared__ __align__(128) char sm[3 * YSTAGE];
    const uint32_t sb = smem_u32(sm);
    const int tid = threadIdx.x, wid = tid >> 5, lane = tid & 31;
    const int b = blockIdx.x, st = blockIdx.y;
    const int a = act[b];
    const int wm = wid & 3, wn = wid >> 2;

    float acc[4][4] = {};

    y_load(0, tid, sb, b, st, a); CP_COMMIT();
    y_load(1, tid, sb, b, st, a); CP_COMMIT();

    for (int c = 0; c < 4; c++) {
        if (c + 2 < 4) y_load(c + 2, tid, sb, b, st, a);
        CP_COMMIT();
        CP_WAIT2();
        __syncthreads();
        const uint32_t ab = sb + (c % 3) * YSTAGE;
        const uint32_t bb = ab + 8192;
#pragma unroll
        for (int ks = 0; ks < 4; ks++) {
            const int k8 = ks * 2 + (lane >> 4);
            uint32_t afr[4];
            {
                int r = wm * 16 + (lane & 15);
                ldsm4(afr, ab + r * 128 + ((k8 ^ (r & 7)) << 4));
            }
            uint32_t bfr[4][2];
#pragma unroll
            for (int np = 0; np < 2; np++) {
                int r = wn * 32 + np * 16 + (lane & 15);
                uint32_t t[4];
                ldsm4(t, bb + r * 128 + ((k8 ^ (r & 7)) << 4));
                bfr[np * 2][0] = t[0]; bfr[np * 2 + 1][0] = t[1];
                bfr[np * 2][1] = t[2]; bfr[np * 2 + 1][1] = t[3];
            }
#pragma unroll
            for (int nt2 = 0; nt2 < 4; nt2++)
                mma16816(acc[nt2], afr, bfr[nt2]);
        }
        __syncthreads();
    }

    const int s = st * 64 + wm * 16 + (lane >> 2);
    const int n0 = wn * 32 + (lane & 3) * 2;
#pragma unroll
    for (int nt2 = 0; nt2 < 4; nt2++) {
        int n = n0 + nt2 * 8;
        float b0 = b2[a * DKc + n], b1v = b2[a * DKc + n + 1];
        float* dst = g_yt + ((size_t)b * Sc + s) * DKc + n;
        *reinterpret_cast<float2*>(dst) =
            make_float2(acc[nt2][0] + b0, acc[nt2][1] + b1v);
        *reinterpret_cast<float2*>(dst + 8 * DKc) =
            make_float2(acc[nt2][2] + b0, acc[nt2][3] + b1v);
    }
}

// ---------------------------------------------------------------------------
// Attention scores+softmax (slim): reads g_yt + g_xtT, writes g_att only.
// ---------------------------------------------------------------------------
__global__ void __launch_bounds__(256) k_attn(
        const unsigned char* __restrict__ mask,
        const int* __restrict__ act,
        const float* __restrict__ v) {
    const int s0 = blockIdx.x * GRP;
    const int b = blockIdx.y;
    const int a = act[b];
    const int tid = threadIdx.x;

    __shared__ __align__(16) float yt2[DKc][GRP];
    __shared__ float vv[DKc];
    __shared__ float red[8][GRP];
    __shared__ float ginv[GRP];

    const bool msk = mask[b * Sc + tid];
    if (tid < DKc) vv[tid] = v[a * DKc + tid];
    for (int idx = tid; idx < DKc * GRP; idx += 256) {
        int k = idx >> 3, g = idx & 7;
        yt2[k][g] = g_yt[((size_t)b * Sc + s0 + g) * DKc + k];
    }
    __syncthreads();

    float sc[GRP] = {};
    {
        const float* xt = g_xtT + b * (DKc * Sc);
        for (int k0 = 0; k0 < DKc; k0 += 8) {
            float xvv[8];
#pragma unroll
            for (int kk = 0; kk < 8; kk++)
                xvv[kk] = xt[(k0 + kk) * Sc + tid];
#pragma unroll
            for (int kk = 0; kk < 8; kk++) {
                const int k = k0 + kk;
                const float vk = vv[k];
                const float xv = xvv[kk];
                float4 y0 = *reinterpret_cast<const float4*>(&yt2[k][0]);
                float4 y1 = *reinterpret_cast<const float4*>(&yt2[k][4]);
                sc[0] = fmaf(vk, tanh_fast(xv + y0.x), sc[0]);
                sc[1] = fmaf(vk, tanh_fast(xv + y0.y), sc[1]);
                sc[2] = fmaf(vk, tanh_fast(xv + y0.z), sc[2]);
                sc[3] = fmaf(vk, tanh_fast(xv + y0.w), sc[3]);
                sc[4] = fmaf(vk, tanh_fast(xv + y1.x), sc[4]);
                sc[5] = fmaf(vk, tanh_fast(xv + y1.y), sc[5]);
                sc[6] = fmaf(vk, tanh_fast(xv + y1.z), sc[6]);
                sc[7] = fmaf(vk, tanh_fast(xv + y1.w), sc[7]);
            }
        }
    }

    const int lane = tid & 31, wid = tid >> 5;
    float ex[GRP];
#pragma unroll
    for (int g = 0; g < GRP; g++) ex[g] = msk ? 0.0f : __expf(sc[g]);
#pragma unroll
    for (int g = 0; g < GRP; g++) {
        float s = ex[g];
#pragma unroll
        for (int o = 16; o > 0; o >>= 1) s += __shfl_xor_sync(0xffffffffu, s, o);
        if (lane == 0) red[wid][g] = s;
    }
    __syncthreads();
    if (tid < GRP) {
        float s = red[0][tid];
#pragma unroll
        for (int w = 1; w < 8; w++) s += red[w][tid];
        ginv[tid] = 1.0f / s;
    }
    __syncthreads();

#pragma unroll
    for (int g = 0; g < GRP; g++)
        g_att[((size_t)b * Sc + s0 + g) * Sc + tid] = __float2half(ex[g] * ginv[g]);
}

// ---------------------------------------------------------------------------
// Pools GEMM: pools = att @ x (HMMA), writes fp16 into g_Ah[...,256+d]
// ---------------------------------------------------------------------------
__device__ __forceinline__ void p_load(int c, int tid, uint32_t sb,
                                       int b, int st, int nt) {
    const int l0 = c << 5;
    const uint32_t ab = sb + (c % 3) * PSTAGE;
    const uint32_t bb = ab + 4096;
    {
        int r = tid >> 2, ch = tid & 3;
        const __half* src = g_att + ((size_t)b * Sc + st * 64 + r) * Sc + l0 + ch * 8;
        cp16(ab + r * 64 + ((ch ^ (r & 3)) << 4), src);
    }
#pragma unroll
    for (int i = 0; i < 2; i++) {
        int v = tid + i * 256, r = v >> 4, ch = v & 15;
        const __half* src = g_xh + ((size_t)b * Sc + l0 + r) * Dc + nt * 128 + ch * 8;
        cp16(bb + r * 256 + ((ch ^ (r & 15)) << 4), src);
    }
}

__global__ void __launch_bounds__(256) k_pool() {
    __shared__ __align__(128) char sm[3 * PSTAGE];
    const uint32_t sb = smem_u32(sm);
    const int tid = threadIdx.x, wid = tid >> 5, lane = tid & 31;
    const int b = blockIdx.x, st = blockIdx.y, nt = blockIdx.z;
    const int wm = wid & 1, wn = wid >> 1;

    float acc[2][4][4] = {};

    p_load(0, tid, sb, b, st, nt); CP_COMMIT();
    p_load(1, tid, sb, b, st, nt); CP_COMMIT();

    for (int c = 0; c < 8; c++) {
        if (c + 2 < 8) p_load(c + 2, tid, sb, b, st, nt);
        CP_COMMIT();
        CP_WAIT2();
        __syncthreads();

        const uint32_t ab = sb + (c % 3) * PSTAGE;
        const uint32_t bb = ab + 4096;
#pragma unroll
        for (int ks = 0; ks < 2; ks++) {
            uint32_t a[2][4];
#pragma unroll
            for (int mt2 = 0; mt2 < 2; mt2++) {
                int r = wm * 32 + mt2 * 16 + (lane & 15);
                int k8 = ks * 2 + (lane >> 4);
                ldsm4(a[mt2], ab + r * 64 + ((k8 ^ (r & 3)) << 4));
            }
            uint32_t bf[4][2];
#pragma unroll
            for (int ng = 0; ng < 2; ng++) {
                int r = ks * 16 + (lane & 15);
                int ch = wn * 4 + ng * 2 + (lane >> 4);
                uint32_t t[4];
                ldsm4t(t, bb + r * 256 + ((ch ^ (r & 15)) << 4));
                bf[ng * 2][0] = t[0]; bf[ng * 2][1] = t[1];
                bf[ng * 2 + 1][0] = t[2]; bf[ng * 2 + 1][1] = t[3];
            }
#pragma unroll
            for (int mt2 = 0; mt2 < 2; mt2++)
#pragma unroll
                for (int oct = 0; oct < 4; oct++)
                    mma16816(acc[mt2][oct], a[mt2], bf[oct]);
        }
        __syncthreads();
    }

    const int s_b = st * 64 + wm * 32 + (lane >> 2);
    const int d_b = nt * 128 + wn * 32 + (lane & 3) * 2;
#pragma unroll
    for (int mt2 = 0; mt2 < 2; mt2++) {
#pragma unroll
        for (int oct = 0; oct < 4; oct++) {
            int s = s_b + mt2 * 16, d = d_b + oct * 8;
            __half2 h01 = __floats2half2_rn(acc[mt2][oct][0], acc[mt2][oct][1]);
            __half2 h23 = __floats2half2_rn(acc[mt2][oct][2], acc[mt2][oct][3]);
            *reinterpret_cast<__half2*>(&g_Ah[(size_t)(s * Bc + b) * NIN + Dc + d]) = h01;
            *reinterpret_cast<__half2*>(&g_Ah[(size_t)((s + 8) * Bc + b) * NIN + Dc + d]) = h23;
        }
    }
}

// ---------------------------------------------------------------------------
// HMMA GEMM: U = Ah @ Wh^T
// ---------------------------------------------------------------------------
__device__ __forceinline__ void g_load(int c, int tid, uint32_t sb,
                                       int mt, int nt, int layer) {
    const int kc = c << 5;
    const __half* Ap = g_Ah + (size_t)(mt * 128) * NIN + kc;
    const __half* Bp = g_Wh + (size_t)(layer * NJ + nt * 128) * NIN + kc;
    const uint32_t ab = sb + (c % 3) * STAGE;
    const uint32_t bb = ab + STG_A;
#pragma unroll
    for (int i = 0; i < 2; i++) {
        int vi = tid + i * 256, r = vi >> 2, ch = vi & 3;
        cp16(ab + r * 64 + ((ch ^ (r & 3)) << 4), Ap + (size_t)r * NIN + ch * 8);
    }
#pragma unroll
    for (int i = 0; i < 2; i++) {
        int vi = tid + i * 256, r = vi >> 2, ch = vi & 3;
        cp16(bb + r * 64 + ((ch ^ (r & 3)) << 4), Bp + (size_t)r * NIN + ch * 8);
    }
}

__global__ void __launch_bounds__(256) k_wgemm(int layer) {
    __shared__ __align__(128) char sm[3 * STAGE];
    const uint32_t sb = smem_u32(sm);
    const int tid = threadIdx.x, wid = tid >> 5, lane = tid & 31;
    const int mt = blockIdx.x, nt = blockIdx.y;
    const int wm = wid & 3, wn = wid >> 2;

    float acc[2][8][4] = {};

    g_load(0, tid, sb, mt, nt, layer); CP_COMMIT();
    g_load(1, tid, sb, mt, nt, layer); CP_COMMIT();

    const int arow_b = wm * 32 + (lane & 15);
    const int brow_b = wn * 64 + (lane & 15);
    const int khalf = lane >> 4;

    for (int c = 0; c < NIT; c++) {
        if (c + 2 < NIT) g_load(c + 2, tid, sb, mt, nt, layer);
        CP_COMMIT();
        CP_WAIT2();
        __syncthreads();

        const uint32_t ab = sb + (c % 3) * STAGE;
        const uint32_t bb = ab + STG_A;
#pragma unroll
        for (int ks = 0; ks < 2; ks++) {
            const int k8 = ks * 2 + khalf;
            uint32_t a[2][4], b[8][2];
#pragma unroll
            for (int mtile = 0; mtile < 2; mtile++) {
                int r = arow_b + mtile * 16;
                ldsm4(a[mtile], ab + r * 64 + ((k8 ^ (r & 3)) << 4));
            }
#pragma unroll
            for (int np = 0; np < 4; np++) {
                int r = brow_b + np * 16;
                uint32_t t[4];
                ldsm4(t, bb + r * 64 + ((k8 ^ (r & 3)) << 4));
                b[np * 2][0] = t[0]; b[np * 2 + 1][0] = t[1];
                b[np * 2][1] = t[2]; b[np * 2 + 1][1] = t[3];
            }
#pragma unroll
            for (int mtile = 0; mtile < 2; mtile++)
#pragma unroll
                for (int ntile = 0; ntile < 8; ntile++)
                    mma16816(acc[mtile][ntile], a[mtile], b[ntile]);
        }
        __syncthreads();
    }

    const int m_b = mt * 128 + wm * 32 + (lane >> 2);
    const int n_b = nt * 128 + wn * 64 + (lane & 3) * 2;
#pragma unroll
    for (int mtile = 0; mtile < 2; mtile++) {
#pragma unroll
        for (int ntile = 0; ntile < 8; ntile++) {
            float* dst = g_U + (size_t)(m_b + mtile * 16) * NJ + n_b + ntile * 8;
            *reinterpret_cast<float2*>(dst) =
                make_float2(acc[mtile][ntile][0], acc[mtile][ntile][1]);
            *reinterpret_cast<float2*>(dst + 8 * NJ) =
                make_float2(acc[mtile][ntile][2], acc[mtile][ntile][3]);
        }
    }
}

// ---------------------------------------------------------------------------
// SRU chunked-parallel scan with batched prefetch
// ---------------------------------------------------------------------------
__global__ void k_scanA(const float* __restrict__ bfv, const float* __restrict__ bbv,
                        int layer) {
    const int ch = blockIdx.x, by = blockIdx.y;
    const int b = by >> 1, dir = by & 1;
    const int h = threadIdx.x;
    const float bf = ((dir == 0 ? bfv : bbv) + layer * 2 * Hc)[h];
    const float* base = g_U + ((size_t)(ch * CHS) * Bc + b) * NJ + dir * 512 + h;

    float u0v[CHS], ufv[CHS];
#pragma unroll
    for (int s = 0; s < CHS; s++) {
        const float* u = base + (size_t)s * (Bc * NJ);
        u0v[s] = u[0];
        ufv[s] = u[128];
    }
    float c = 0.0f, P = 1.0f;
#pragma unroll
    for (int s = 0; s < CHS; s++) {
        float f = sig_fast(ufv[s] + bf);
        c = u0v[s] + f * (c - u0v[s]);
        P *= f;
    }
    const int idx = (ch * 32 + by) * Hc + h;
    g_cend[idx] = c;
    g_P[idx] = P;
}

__global__ void k_scanC(const float* __restrict__ bfv, const float* __restrict__ bbv,
                        int layer, int is_last, float* __restrict__ out_final) {
    const int ch = blockIdx.x, by = blockIdx.y;
    const int b = by >> 1, dir = by & 1;
    const int h = threadIdx.x;
    const float* bias = (dir == 0 ? bfv : bbv) + layer * 2 * Hc;
    const float bf = bias[h];
    const float br = bias[Hc + h];
    const float* base = g_U + ((size_t)(ch * CHS) * Bc + b) * NJ + dir * 512 + h;

    float c = 0.0f;
    {
        float Pa[NCH - 1], Ca[NCH - 1];
#pragma unroll
        for (int i = 0; i < NCH - 1; i++) {
            if (i < ch) {
                const int idx = (i * 32 + by) * Hc + h;
                Pa[i] = g_P[idx];
                Ca[i] = g_cend[idx];
            }
        }
#pragma unroll
        for (int i = 0; i < NCH - 1; i++)
            if (i < ch) c = Pa[i] * c + Ca[i];
    }

#pragma unroll
    for (int half = 0; half < 2; half++) {
        float u0v[8], ufv[8], urv[8], hwv[8];
#pragma unroll
        for (int s = 0; s < 8; s++) {
            const float* u = base + (size_t)(half * 8 + s) * (Bc * NJ);
            u0v[s] = u[0]; ufv[s] = u[128]; urv[s] = u[256]; hwv[s] = u[384];
        }
#pragma unroll
        for (int s = 0; s < 8; s++) {
            float f = sig_fast(ufv[s] + bf);
            float r = sig_fast(urv[s] + br);
            c = u0v[s] + f * (c - u0v[s]);
            float hv = hwv[s] + r * (tanh_fast(c) - hwv[s]);
            const int s_abs = ch * CHS + half * 8 + s;
            if (is_last)
                out_final[b * (Sc * Dc) + s_abs * Dc + dir * Hc + h] = hv;
            else
                g_Ah[(size_t)(s_abs * Bc + b) * NIN + dir * Hc + h] = __float2half(hv);
        }
    }
}

// ---------------------------------------------------------------------------
extern "C" void kernel_launch(void* const* d_in, const int* in_sizes, int n_in,
                              void* d_out, int out_size) {
    const float* x            = (const float*)d_in[0];
    const unsigned char* mask = (const unsigned char*)d_in[1];
    const int* act            = (const int*)d_in[2];
    const float* w1           = (const float*)d_in[3];
    const float* b1           = (const float*)d_in[4];
    const float* w2           = (const float*)d_in[5];
    const float* b2           = (const float*)d_in[6];
    const float* v            = (const float*)d_in[7];
    const float* swf          = (const float*)d_in[8];
    const float* sbf          = (const float*)d_in[9];
    const float* swb          = (const float*)d_in[10];
    const float* sbb          = (const float*)d_in[11];
    float* out = (float*)d_out;

    k_prep<<<2176, 256>>>(x, swf, swb, w2, w1);
    k_xtg<<<dim3(Bc, 4), 256>>>(act, b1);

    for (int layer = 0; layer < 2; layer++) {
        k_ytg<<<dim3(Bc, 4), 256>>>(act, b2);
        k_attn<<<dim3(Sc / GRP, Bc), 256>>>(mask, act, v);
        k_pool<<<dim3(Bc, 4, 2), 256>>>();
        k_wgemm<<<dim3(32, 8), 256>>>(layer);
        k_scanA<<<dim3(NCH, 32), Hc>>>(sbf, sbb, layer);
        k_scanC<<<dim3(NCH, 32), Hc>>>(sbf, sbb, layer, layer == 1 ? 1 : 0, out);
    }
}

// round 16
// speedup vs baseline: 1.1454x; 1.0487x over previous
#include <cuda_runtime.h>
#include <cuda_fp16.h>
#include <math.h>
#include <stdint.h>

#define Bc   16
#define Sc   256
#define Dc   256
#define Hc   128
#define DKc  64
#define NIN  512
#define NJ   1024
#define GRP  4
#define NCH  16
#define CHS  16

// wgemm config
#define NIT    16
#define STG_A  8192
#define STAGE  16384
// pool-gemm config
#define PSTAGE 12288
// yt/xt-gemm config
#define YSTAGE 16384

// ---------------- scratch -----------------
__device__ float g_xtT[Bc * DKc * Sc];
__device__ float g_U[Sc * Bc * NJ];
__device__ float g_cend[NCH * 32 * Hc];
__device__ float g_P[NCH * 32 * Hc];
__device__ float g_yt[Bc * Sc * DKc];                  // [b][s][k]
__device__ __align__(256) __half g_Ah[Sc * Bc * NIN];  // rows ++ pools (fp16)
__device__ __align__(256) __half g_Wh[2 * NJ * NIN];   // [layer][n][k]
__device__ __align__(256) __half g_w2h[8 * DKc * Dc];  // [a][k][d]
__device__ __align__(256) __half g_w1h[8 * DKc * Dc];  // [a][k][d]
__device__ __align__(256) __half g_att[Bc * Sc * Sc];  // [b][s][l]
__device__ __align__(256) __half g_xh[Bc * Sc * Dc];   // x as fp16

// ---------------- helpers -----------------
__device__ __forceinline__ float tanh_fast(float x) {
    float y; asm("tanh.approx.f32 %0, %1;" : "=f"(y) : "f"(x)); return y;
}
__device__ __forceinline__ float sig_fast(float x) {
    float e, r;
    asm("ex2.approx.f32 %0, %1;" : "=f"(e) : "f"(x * -1.4426950408889634f));
    asm("rcp.approx.f32 %0, %1;" : "=f"(r) : "f"(1.0f + e));
    return r;
}
__device__ __forceinline__ uint32_t smem_u32(const void* p) {
    uint32_t a;
    asm("{ .reg .u64 t; cvta.to.shared.u64 t, %1; cvt.u32.u64 %0, t; }" : "=r"(a) : "l"(p));
    return a;
}
__device__ __forceinline__ void cp16(uint32_t d, const void* s) {
    asm volatile("cp.async.cg.shared.global [%0], [%1], 16;\n" :: "r"(d), "l"(s));
}
#define CP_COMMIT() asm volatile("cp.async.commit_group;\n" ::: "memory")
#define CP_WAIT2()  asm volatile("cp.async.wait_group 2;\n" ::: "memory")

__device__ __forceinline__ void ldsm4(uint32_t* r, uint32_t addr) {
    asm volatile("ldmatrix.sync.aligned.m8n8.x4.shared.b16 {%0,%1,%2,%3}, [%4];"
                 : "=r"(r[0]), "=r"(r[1]), "=r"(r[2]), "=r"(r[3]) : "r"(addr));
}
__device__ __forceinline__ void ldsm4t(uint32_t* r, uint32_t addr) {
    asm volatile("ldmatrix.sync.aligned.m8n8.x4.trans.shared.b16 {%0,%1,%2,%3}, [%4];"
                 : "=r"(r[0]), "=r"(r[1]), "=r"(r[2]), "=r"(r[3]) : "r"(addr));
}
__device__ __forceinline__ void mma16816(float* c, const uint32_t* a, const uint32_t* b) {
    asm volatile("mma.sync.aligned.m16n8k16.row.col.f32.f16.f16.f32 "
                 "{%0,%1,%2,%3}, {%4,%5,%6,%7}, {%8,%9}, {%0,%1,%2,%3};"
                 : "+f"(c[0]), "+f"(c[1]), "+f"(c[2]), "+f"(c[3])
                 : "r"(a[0]), "r"(a[1]), "r"(a[2]), "r"(a[3]), "r"(b[0]), "r"(b[1]));
}

// ---------------------------------------------------------------------------
// k_prep: merged prep dispatch.
//   blocks [0,1024):    x -> fp16 g_xh + layer-0 rows into g_Ah
//   blocks [1024,2048): SRU weight convert/transpose -> g_Wh
//   blocks [2048,2176): w2/w1 convert/transpose -> g_w2h / g_w1h
// ---------------------------------------------------------------------------
__global__ void __launch_bounds__(256) k_prep(
        const float* __restrict__ x,
        const float* __restrict__ wf, const float* __restrict__ wb,
        const float* __restrict__ w2, const float* __restrict__ w1) {
    __shared__ float t[32][65];
    const int blk = blockIdx.x, tid = threadIdx.x;

    if (blk < 1024) {
        const int e = (blk * 256 + tid) * 4;
        float4 v = *reinterpret_cast<const float4*>(x + e);
        __half2 h0 = __floats2half2_rn(v.x, v.y);
        __half2 h1 = __floats2half2_rn(v.z, v.w);
        *reinterpret_cast<__half2*>(&g_xh[e])     = h0;
        *reinterpret_cast<__half2*>(&g_xh[e + 2]) = h1;
        const int b = e >> 16, s = (e >> 8) & 255, d = e & 255;
        const size_t idx = (size_t)(s * Bc + b) * NIN + d;
        *reinterpret_cast<__half2*>(&g_Ah[idx])     = h0;
        *reinterpret_cast<__half2*>(&g_Ah[idx + 2]) = h1;
    } else if (blk < 2048) {
        const int idx = blk - 1024;
        const int k0 = (idx & 15) * 32;
        const int nt = ((idx >> 4) & 31) * 32;
        const int l = idx >> 9;
        const float* W = (nt < 512) ? (wf + l * 262144 + nt)
                                    : (wb + l * 262144 + (nt - 512));
        const int tx = tid & 31, ty = tid >> 5;
        for (int i = ty; i < 32; i += 8)
            t[i][tx] = W[(k0 + i) * 512 + tx];
        __syncthreads();
        for (int i = ty; i < 32; i += 8) {
            size_t o = (size_t)(l * NJ + nt + i) * NIN + k0 + tx;
            g_Wh[o] = __float2half(t[tx][i]);
        }
    } else {
        const int idx = blk - 2048;            // [0,128): 64 w2 then 64 w1
        const float* W = (idx < 64) ? w2 : w1;
        __half* dst = (idx < 64) ? g_w2h : g_w1h;
        const int a = (idx & 63) >> 3, dt = idx & 7;
        for (int i = tid; i < 2048; i += 256) {
            int d = i >> 6, kk = i & 63;
            t[d][kk] = W[((size_t)a * Dc + dt * 32 + d) * DKc + kk];
        }
        __syncthreads();
        for (int i = tid; i < 2048; i += 256) {
            int kk = i >> 5, d = i & 31;
            dst[((size_t)a * DKc + kk) * Dc + dt * 32 + d] = __float2half(t[d][kk]);
        }
    }
}

// ---------------------------------------------------------------------------
// xt GEMM (HMMA): g_xtT[b][k][l] = x[b,l,:] @ w1a[:,k] + b1
// ---------------------------------------------------------------------------
__device__ __forceinline__ void x_load(int c, int tid, uint32_t sb, int b, int lt, int a) {
    const int d0 = c << 6;
    const uint32_t ab = sb + (c % 3) * YSTAGE;
    const uint32_t bb = ab + 8192;
#pragma unroll
    for (int i = 0; i < 2; i++) {
        int v = tid + i * 256, r = v >> 3, ch = v & 7;
        const __half* src = g_xh + (size_t)(b * Sc + lt * 64 + r) * Dc + d0 + ch * 8;
        cp16(ab + r * 128 + ((ch ^ (r & 7)) << 4), src);
    }
#pragma unroll
    for (int i = 0; i < 2; i++) {
        int v = tid + i * 256, r = v >> 3, ch = v & 7;
        const __half* src = g_w1h + (size_t)(a * DKc + r) * Dc + d0 + ch * 8;
        cp16(bb + r * 128 + ((ch ^ (r & 7)) << 4), src);
    }
}

__global__ void __launch_bounds__(256) k_xtg(const int* __restrict__ act,
                                             const float* __restrict__ b1) {
    __shared__ __align__(128) char sm[3 * YSTAGE];
    const uint32_t sb = smem_u32(sm);
    const int tid = threadIdx.x, wid = tid >> 5, lane = tid & 31;
    const int b = blockIdx.x, lt = blockIdx.y;
    const int a = act[b];
    const int wm = wid & 3, wn = wid >> 2;

    float acc[4][4] = {};

    x_load(0, tid, sb, b, lt, a); CP_COMMIT();
    x_load(1, tid, sb, b, lt, a); CP_COMMIT();

    for (int c = 0; c < 4; c++) {
        if (c + 2 < 4) x_load(c + 2, tid, sb, b, lt, a);
        CP_COMMIT();
        CP_WAIT2();
        __syncthreads();
        const uint32_t ab = sb + (c % 3) * YSTAGE;
        const uint32_t bb = ab + 8192;
#pragma unroll
        for (int ks = 0; ks < 4; ks++) {
            const int k8 = ks * 2 + (lane >> 4);
            uint32_t afr[4];
            {
                int r = wm * 16 + (lane & 15);
                ldsm4(afr, ab + r * 128 + ((k8 ^ (r & 7)) << 4));
            }
            uint32_t bfr[4][2];
#pragma unroll
            for (int np = 0; np < 2; np++) {
                int r = wn * 32 + np * 16 + (lane & 15);
                uint32_t t[4];
                ldsm4(t, bb + r * 128 + ((k8 ^ (r & 7)) << 4));
                bfr[np * 2][0] = t[0]; bfr[np * 2 + 1][0] = t[1];
                bfr[np * 2][1] = t[2]; bfr[np * 2 + 1][1] = t[3];
            }
#pragma unroll
            for (int nt2 = 0; nt2 < 4; nt2++)
                mma16816(acc[nt2], afr, bfr[nt2]);
        }
        __syncthreads();
    }

    const int l = lt * 64 + wm * 16 + (lane >> 2);
    const int n0 = wn * 32 + (lane & 3) * 2;
    float* xt = g_xtT + b * (DKc * Sc);
#pragma unroll
    for (int nt2 = 0; nt2 < 4; nt2++) {
        int n = n0 + nt2 * 8;
        float b0 = b1[a * DKc + n], b1v = b1[a * DKc + n + 1];
        xt[n * Sc + l]           = acc[nt2][0] + b0;
        xt[(n + 1) * Sc + l]     = acc[nt2][1] + b1v;
        xt[n * Sc + l + 8]       = acc[nt2][2] + b0;
        xt[(n + 1) * Sc + l + 8] = acc[nt2][3] + b1v;
    }
}

// ---------------------------------------------------------------------------
// yt GEMM (HMMA): g_yt[b][s][k] = rows(g_Ah) @ w2a^T + b2
// ---------------------------------------------------------------------------
__device__ __forceinline__ void y_load(int c, int tid, uint32_t sb, int b, int st, int a) {
    const int d0 = c << 6;
    const uint32_t ab = sb + (c % 3) * YSTAGE;
    const uint32_t bb = ab + 8192;
#pragma unroll
    for (int i = 0; i < 2; i++) {
        int v = tid + i * 256, r = v >> 3, ch = v & 7;
        const __half* src = g_Ah + (size_t)((st * 64 + r) * Bc + b) * NIN + d0 + ch * 8;
        cp16(ab + r * 128 + ((ch ^ (r & 7)) << 4), src);
    }
#pragma unroll
    for (int i = 0; i < 2; i++) {
        int v = tid + i * 256, r = v >> 3, ch = v & 7;
        const __half* src = g_w2h + (size_t)(a * DKc + r) * Dc + d0 + ch * 8;
        cp16(bb + r * 128 + ((ch ^ (r & 7)) << 4), src);
    }
}

__global__ void __launch_bounds__(256) k_ytg(const int* __restrict__ act,
                                             const float* __restrict__ b2) {
    __shared__ __align__(128) char sm[3 * YSTAGE];
    const uint32_t sb = smem_u32(sm);
    const int tid = threadIdx.x, wid = tid >> 5, lane = tid & 31;
    const int b = blockIdx.x, st = blockIdx.y;
    const int a = act[b];
    const int wm = wid & 3, wn = wid >> 2;

    float acc[4][4] = {};

    y_load(0, tid, sb, b, st, a); CP_COMMIT();
    y_load(1, tid, sb, b, st, a); CP_COMMIT();

    for (int c = 0; c < 4; c++) {
        if (c + 2 < 4) y_load(c + 2, tid, sb, b, st, a);
        CP_COMMIT();
        CP_WAIT2();
        __syncthreads();
        const uint32_t ab = sb + (c % 3) * YSTAGE;
        const uint32_t bb = ab + 8192;
#pragma unroll
        for (int ks = 0; ks < 4; ks++) {
            const int k8 = ks * 2 + (lane >> 4);
            uint32_t afr[4];
            {
                int r = wm * 16 + (lane & 15);
                ldsm4(afr, ab + r * 128 + ((k8 ^ (r & 7)) << 4));
            }
            uint32_t bfr[4][2];
#pragma unroll
            for (int np = 0; np < 2; np++) {
                int r = wn * 32 + np * 16 + (lane & 15);
                uint32_t t[4];
                ldsm4(t, bb + r * 128 + ((k8 ^ (r & 7)) << 4));
                bfr[np * 2][0] = t[0]; bfr[np * 2 + 1][0] = t[1];
                bfr[np * 2][1] = t[2]; bfr[np * 2 + 1][1] = t[3];
            }
#pragma unroll
            for (int nt2 = 0; nt2 < 4; nt2++)
                mma16816(acc[nt2], afr, bfr[nt2]);
        }
        __syncthreads();
    }

    const int s = st * 64 + wm * 16 + (lane >> 2);
    const int n0 = wn * 32 + (lane & 3) * 2;
#pragma unroll
    for (int nt2 = 0; nt2 < 4; nt2++) {
        int n = n0 + nt2 * 8;
        float b0 = b2[a * DKc + n], b1v = b2[a * DKc + n + 1];
        float* dst = g_yt + ((size_t)b * Sc + s) * DKc + n;
        *reinterpret_cast<float2*>(dst) =
            make_float2(acc[nt2][0] + b0, acc[nt2][1] + b1v);
        *reinterpret_cast<float2*>(dst + 8 * DKc) =
            make_float2(acc[nt2][2] + b0, acc[nt2][3] + b1v);
    }
}

// ---------------------------------------------------------------------------
// Attention scores+softmax (slim, GRP=4 for wave balance): reads g_yt + g_xtT,
// writes g_att only. 1024 blocks.
// ---------------------------------------------------------------------------
__global__ void __launch_bounds__(256) k_attn(
        const unsigned char* __restrict__ mask,
        const int* __restrict__ act,
        const float* __restrict__ v) {
    const int s0 = blockIdx.x * GRP;
    const int b = blockIdx.y;
    const int a = act[b];
    const int tid = threadIdx.x;

    __shared__ __align__(16) float yt2[DKc][GRP];
    __shared__ float vv[DKc];
    __shared__ float red[8][GRP];
    __shared__ float ginv[GRP];

    const bool msk = mask[b * Sc + tid];
    if (tid < DKc) vv[tid] = v[a * DKc + tid];
    {
        int k = tid >> 2, g = tid & 3;   // 256 threads cover DKc*GRP exactly
        yt2[k][g] = g_yt[((size_t)b * Sc + s0 + g) * DKc + k];
    }
    __syncthreads();

    float sc[GRP] = {};
    {
        const float* xt = g_xtT + b * (DKc * Sc);
        for (int k0 = 0; k0 < DKc; k0 += 8) {
            float xvv[8];
#pragma unroll
            for (int kk = 0; kk < 8; kk++)
                xvv[kk] = xt[(k0 + kk) * Sc + tid];
#pragma unroll
            for (int kk = 0; kk < 8; kk++) {
                const int k = k0 + kk;
                const float vk = vv[k];
                const float xv = xvv[kk];
                float4 y0 = *reinterpret_cast<const float4*>(&yt2[k][0]);
                sc[0] = fmaf(vk, tanh_fast(xv + y0.x), sc[0]);
                sc[1] = fmaf(vk, tanh_fast(xv + y0.y), sc[1]);
                sc[2] = fmaf(vk, tanh_fast(xv + y0.z), sc[2]);
                sc[3] = fmaf(vk, tanh_fast(xv + y0.w), sc[3]);
            }
        }
    }

    // softmax without max-subtraction (|score| <= sum|v| <= 8)
    const int lane = tid & 31, wid = tid >> 5;
    float ex[GRP];
#pragma unroll
    for (int g = 0; g < GRP; g++) ex[g] = msk ? 0.0f : __expf(sc[g]);
#pragma unroll
    for (int g = 0; g < GRP; g++) {
        float s = ex[g];
#pragma unroll
        for (int o = 16; o > 0; o >>= 1) s += __shfl_xor_sync(0xffffffffu, s, o);
        if (lane == 0) red[wid][g] = s;
    }
    __syncthreads();
    if (tid < GRP) {
        float s = red[0][tid];
#pragma unroll
        for (int w = 1; w < 8; w++) s += red[w][tid];
        ginv[tid] = 1.0f / s;
    }
    __syncthreads();

#pragma unroll
    for (int g = 0; g < GRP; g++)
        g_att[((size_t)b * Sc + s0 + g) * Sc + tid] = __float2half(ex[g] * ginv[g]);
}

// ---------------------------------------------------------------------------
// Pools GEMM: pools = att @ x (HMMA), writes fp16 into g_Ah[...,256+d]
// ---------------------------------------------------------------------------
__device__ __forceinline__ void p_load(int c, int tid, uint32_t sb,
                                       int b, int st, int nt) {
    const int l0 = c << 5;
    const uint32_t ab = sb + (c % 3) * PSTAGE;
    const uint32_t bb = ab + 4096;
    {
        int r = tid >> 2, ch = tid & 3;
        const __half* src = g_att + ((size_t)b * Sc + st * 64 + r) * Sc + l0 + ch * 8;
        cp16(ab + r * 64 + ((ch ^ (r & 3)) << 4), src);
    }
#pragma unroll
    for (int i = 0; i < 2; i++) {
        int v = tid + i * 256, r = v >> 4, ch = v & 15;
        const __half* src = g_xh + ((size_t)b * Sc + l0 + r) * Dc + nt * 128 + ch * 8;
        cp16(bb + r * 256 + ((ch ^ (r & 15)) << 4), src);
    }
}

__global__ void __launch_bounds__(256) k_pool() {
    __shared__ __align__(128) char sm[3 * PSTAGE];
    const uint32_t sb = smem_u32(sm);
    const int tid = threadIdx.x, wid = tid >> 5, lane = tid & 31;
    const int b = blockIdx.x, st = blockIdx.y, nt = blockIdx.z;
    const int wm = wid & 1, wn = wid >> 1;

    float acc[2][4][4] = {};

    p_load(0, tid, sb, b, st, nt); CP_COMMIT();
    p_load(1, tid, sb, b, st, nt); CP_COMMIT();

    for (int c = 0; c < 8; c++) {
        if (c + 2 < 8) p_load(c + 2, tid, sb, b, st, nt);
        CP_COMMIT();
        CP_WAIT2();
        __syncthreads();

        const uint32_t ab = sb + (c % 3) * PSTAGE;
        const uint32_t bb = ab + 4096;
#pragma unroll
        for (int ks = 0; ks < 2; ks++) {
            uint32_t a[2][4];
#pragma unroll
            for (int mt2 = 0; mt2 < 2; mt2++) {
                int r = wm * 32 + mt2 * 16 + (lane & 15);
                int k8 = ks * 2 + (lane >> 4);
                ldsm4(a[mt2], ab + r * 64 + ((k8 ^ (r & 3)) << 4));
            }
            uint32_t bf[4][2];
#pragma unroll
            for (int ng = 0; ng < 2; ng++) {
                int r = ks * 16 + (lane & 15);
                int ch = wn * 4 + ng * 2 + (lane >> 4);
                uint32_t t[4];
                ldsm4t(t, bb + r * 256 + ((ch ^ (r & 15)) << 4));
                bf[ng * 2][0] = t[0]; bf[ng * 2][1] = t[1];
                bf[ng * 2 + 1][0] = t[2]; bf[ng * 2 + 1][1] = t[3];
            }
#pragma unroll
            for (int mt2 = 0; mt2 < 2; mt2++)
#pragma unroll
                for (int oct = 0; oct < 4; oct++)
                    mma16816(acc[mt2][oct], a[mt2], bf[oct]);
        }
        __syncthreads();
    }

    const int s_b = st * 64 + wm * 32 + (lane >> 2);
    const int d_b = nt * 128 + wn * 32 + (lane & 3) * 2;
#pragma unroll
    for (int mt2 = 0; mt2 < 2; mt2++) {
#pragma unroll
        for (int oct = 0; oct < 4; oct++) {
            int s = s_b + mt2 * 16, d = d_b + oct * 8;
            __half2 h01 = __floats2half2_rn(acc[mt2][oct][0], acc[mt2][oct][1]);
            __half2 h23 = __floats2half2_rn(acc[mt2][oct][2], acc[mt2][oct][3]);
            *reinterpret_cast<__half2*>(&g_Ah[(size_t)(s * Bc + b) * NIN + Dc + d]) = h01;
            *reinterpret_cast<__half2*>(&g_Ah[(size_t)((s + 8) * Bc + b) * NIN + Dc + d]) = h23;
        }
    }
}

// ---------------------------------------------------------------------------
// HMMA GEMM: U = Ah @ Wh^T
// ---------------------------------------------------------------------------
__device__ __forceinline__ void g_load(int c, int tid, uint32_t sb,
                                       int mt, int nt, int layer) {
    const int kc = c << 5;
    const __half* Ap = g_Ah + (size_t)(mt * 128) * NIN + kc;
    const __half* Bp = g_Wh + (size_t)(layer * NJ + nt * 128) * NIN + kc;
    const uint32_t ab = sb + (c % 3) * STAGE;
    const uint32_t bb = ab + STG_A;
#pragma unroll
    for (int i = 0; i < 2; i++) {
        int vi = tid + i * 256, r = vi >> 2, ch = vi & 3;
        cp16(ab + r * 64 + ((ch ^ (r & 3)) << 4), Ap + (size_t)r * NIN + ch * 8);
    }
#pragma unroll
    for (int i = 0; i < 2; i++) {
        int vi = tid + i * 256, r = vi >> 2, ch = vi & 3;
        cp16(bb + r * 64 + ((ch ^ (r & 3)) << 4), Bp + (size_t)r * NIN + ch * 8);
    }
}

__global__ void __launch_bounds__(256) k_wgemm(int layer) {
    __shared__ __align__(128) char sm[3 * STAGE];
    const uint32_t sb = smem_u32(sm);
    const int tid = threadIdx.x, wid = tid >> 5, lane = tid & 31;
    const int mt = blockIdx.x, nt = blockIdx.y;
    const int wm = wid & 3, wn = wid >> 2;

    float acc[2][8][4] = {};

    g_load(0, tid, sb, mt, nt, layer); CP_COMMIT();
    g_load(1, tid, sb, mt, nt, layer); CP_COMMIT();

    const int arow_b = wm * 32 + (lane & 15);
    const int brow_b = wn * 64 + (lane & 15);
    const int khalf = lane >> 4;

    for (int c = 0; c < NIT; c++) {
        if (c + 2 < NIT) g_load(c + 2, tid, sb, mt, nt, layer);
        CP_COMMIT();
        CP_WAIT2();
        __syncthreads();

        const uint32_t ab = sb + (c % 3) * STAGE;
        const uint32_t bb = ab + STG_A;
#pragma unroll
        for (int ks = 0; ks < 2; ks++) {
            const int k8 = ks * 2 + khalf;
            uint32_t a[2][4], b[8][2];
#pragma unroll
            for (int mtile = 0; mtile < 2; mtile++) {
                int r = arow_b + mtile * 16;
                ldsm4(a[mtile], ab + r * 64 + ((k8 ^ (r & 3)) << 4));
            }
#pragma unroll
            for (int np = 0; np < 4; np++) {
                int r = brow_b + np * 16;
                uint32_t t[4];
                ldsm4(t, bb + r * 64 + ((k8 ^ (r & 3)) << 4));
                b[np * 2][0] = t[0]; b[np * 2 + 1][0] = t[1];
                b[np * 2][1] = t[2]; b[np * 2 + 1][1] = t[3];
            }
#pragma unroll
            for (int mtile = 0; mtile < 2; mtile++)
#pragma unroll
                for (int ntile = 0; ntile < 8; ntile++)
                    mma16816(acc[mtile][ntile], a[mtile], b[ntile]);
        }
        __syncthreads();
    }

    const int m_b = mt * 128 + wm * 32 + (lane >> 2);
    const int n_b = nt * 128 + wn * 64 + (lane & 3) * 2;
#pragma unroll
    for (int mtile = 0; mtile < 2; mtile++) {
#pragma unroll
        for (int ntile = 0; ntile < 8; ntile++) {
            float* dst = g_U + (size_t)(m_b + mtile * 16) * NJ + n_b + ntile * 8;
            *reinterpret_cast<float2*>(dst) =
                make_float2(acc[mtile][ntile][0], acc[mtile][ntile][1]);
            *reinterpret_cast<float2*>(dst + 8 * NJ) =
                make_float2(acc[mtile][ntile][2], acc[mtile][ntile][3]);
        }
    }
}

// ---------------------------------------------------------------------------
// SRU chunked-parallel scan with batched prefetch
// ---------------------------------------------------------------------------
__global__ void k_scanA(const float* __restrict__ bfv, const float* __restrict__ bbv,
                        int layer) {
    const int ch = blockIdx.x, by = blockIdx.y;
    const int b = by >> 1, dir = by & 1;
    const int h = threadIdx.x;
    const float bf = ((dir == 0 ? bfv : bbv) + layer * 2 * Hc)[h];
    const float* base = g_U + ((size_t)(ch * CHS) * Bc + b) * NJ + dir * 512 + h;

    float u0v[CHS], ufv[CHS];
#pragma unroll
    for (int s = 0; s < CHS; s++) {
        const float* u = base + (size_t)s * (Bc * NJ);
        u0v[s] = u[0];
        ufv[s] = u[128];
    }
    float c = 0.0f, P = 1.0f;
#pragma unroll
    for (int s = 0; s < CHS; s++) {
        float f = sig_fast(ufv[s] + bf);
        c = u0v[s] + f * (c - u0v[s]);
        P *= f;
    }
    const int idx = (ch * 32 + by) * Hc + h;
    g_cend[idx] = c;
    g_P[idx] = P;
}

__global__ void k_scanC(const float* __restrict__ bfv, const float* __restrict__ bbv,
                        int layer, int is_last, float* __restrict__ out_final) {
    const int ch = blockIdx.x, by = blockIdx.y;
    const int b = by >> 1, dir = by & 1;
    const int h = threadIdx.x;
    const float* bias = (dir == 0 ? bfv : bbv) + layer * 2 * Hc;
    const float bf = bias[h];
    const float br = bias[Hc + h];
    const float* base = g_U + ((size_t)(ch * CHS) * Bc + b) * NJ + dir * 512 + h;

    float c = 0.0f;
    {
        float Pa[NCH - 1], Ca[NCH - 1];
#pragma unroll
        for (int i = 0; i < NCH - 1; i++) {
            if (i < ch) {
                const int idx = (i * 32 + by) * Hc + h;
                Pa[i] = g_P[idx];
                Ca[i] = g_cend[idx];
            }
        }
#pragma unroll
        for (int i = 0; i < NCH - 1; i++)
            if (i < ch) c = Pa[i] * c + Ca[i];
    }

#pragma unroll
    for (int half = 0; half < 2; half++) {
        float u0v[8], ufv[8], urv[8], hwv[8];
#pragma unroll
        for (int s = 0; s < 8; s++) {
            const float* u = base + (size_t)(half * 8 + s) * (Bc * NJ);
            u0v[s] = u[0]; ufv[s] = u[128]; urv[s] = u[256]; hwv[s] = u[384];
        }
#pragma unroll
        for (int s = 0; s < 8; s++) {
            float f = sig_fast(ufv[s] + bf);
            float r = sig_fast(urv[s] + br);
            c = u0v[s] + f * (c - u0v[s]);
            float hv = hwv[s] + r * (tanh_fast(c) - hwv[s]);
            const int s_abs = ch * CHS + half * 8 + s;
            if (is_last)
                out_final[b * (Sc * Dc) + s_abs * Dc + dir * Hc + h] = hv;
            else
                g_Ah[(size_t)(s_abs * Bc + b) * NIN + dir * Hc + h] = __float2half(hv);
        }
    }
}

// ---------------------------------------------------------------------------
extern "C" void kernel_launch(void* const* d_in, const int* in_sizes, int n_in,
                              void* d_out, int out_size) {
    const float* x            = (const float*)d_in[0];
    const unsigned char* mask = (const unsigned char*)d_in[1];
    const int* act            = (const int*)d_in[2];
    const float* w1           = (const float*)d_in[3];
    const float* b1           = (const float*)d_in[4];
    const float* w2           = (const float*)d_in[5];
    const float* b2           = (const float*)d_in[6];
    const float* v            = (const float*)d_in[7];
    const float* swf          = (const float*)d_in[8];
    const float* sbf          = (const float*)d_in[9];
    const float* swb          = (const float*)d_in[10];
    const float* sbb          = (const float*)d_in[11];
    float* out = (float*)d_out;

    k_prep<<<2176, 256>>>(x, swf, swb, w2, w1);
    k_xtg<<<dim3(Bc, 4), 256>>>(act, b1);

    for (int layer = 0; layer < 2; layer++) {
        k_ytg<<<dim3(Bc, 4), 256>>>(act, b2);
        k_attn<<<dim3(Sc / GRP, Bc), 256>>>(mask, act, v);
        k_pool<<<dim3(Bc, 4, 2), 256>>>();
        k_wgemm<<<dim3(32, 8), 256>>>(layer);
        k_scanA<<<dim3(NCH, 32), Hc>>>(sbf, sbb, layer);
        k_scanC<<<dim3(NCH, 32), Hc>>>(sbf, sbb, layer, layer == 1 ? 1 : 0, out);
    }
}